// round 8
// baseline (speedup 1.0000x reference)
#include <cuda_runtime.h>
#include <cuda_bf16.h>
#include <cstdint>
#include <math.h>

#define BATCH 8
#define NB 2000
#define KC 64
#define FB 128
#define NPAD 2048          // padded n for s^T
#define NCH 32             // ceil(2000/64)

// ---- scratch (device globals: allocation-free) ----
__device__ float g_q[BATCH * NB];                            // per-row sum s^2
__device__ __align__(16) unsigned short g_sTh[BATCH * KC * NPAD]; // s^T hi bf16
__device__ __align__(16) unsigned short g_sTl[BATCH * KC * NPAD]; // s^T lo bf16
__device__ float g_dflat[BATCH * NB];                        // degree
__device__ float g_outadj[BATCH * KC * KC];                  // s^T A s (raw)
__device__ float g_ss[BATCH * KC * KC];                      // s^T s
__device__ float g_bloss[2 * BATCH];                         // per-batch losses

// ================= helpers =================
__device__ __forceinline__ uint32_t smem_to_u32(const void* p) {
    uint32_t a;
    asm("{ .reg .u64 t; cvta.to.shared.u64 t, %1; cvt.u32.u64 %0, t; }" : "=r"(a) : "l"(p));
    return a;
}
#define STSV2(a, v0, v1) \
    asm volatile("st.shared.v2.u32 [%0], {%1,%2};" :: "r"((uint32_t)(a)), "r"(v0), "r"(v1) : "memory")
#define STS32(a, v) \
    asm volatile("st.shared.b32 [%0], %1;" :: "r"((uint32_t)(a)), "r"(v) : "memory")
#define STSV4U(a, v) \
    asm volatile("st.shared.v4.b32 [%0], {%1,%2,%3,%4};" \
                 :: "r"((uint32_t)(a)), "r"((v).x), "r"((v).y), "r"((v).z), "r"((v).w) : "memory")
#define LDSM4(r, a) \
    asm volatile("ldmatrix.sync.aligned.m8n8.x4.shared.b16 {%0,%1,%2,%3}, [%4];" \
        : "=r"((r)[0]), "=r"((r)[1]), "=r"((r)[2]), "=r"((r)[3]) : "r"((uint32_t)(a)))
#define LDSM4T(r, a) \
    asm volatile("ldmatrix.sync.aligned.m8n8.x4.trans.shared.b16 {%0,%1,%2,%3}, [%4];" \
        : "=r"((r)[0]), "=r"((r)[1]), "=r"((r)[2]), "=r"((r)[3]) : "r"((uint32_t)(a)))
#define MMA_BF16(d, a, b0, b1) \
    asm volatile("mma.sync.aligned.m16n8k16.row.col.f32.bf16.bf16.f32 " \
        "{%0,%1,%2,%3}, {%4,%5,%6,%7}, {%8,%9}, {%0,%1,%2,%3};" \
        : "+f"((d)[0]), "+f"((d)[1]), "+f"((d)[2]), "+f"((d)[3]) \
        : "r"((a)[0]), "r"((a)[1]), "r"((a)[2]), "r"((a)[3]), "r"(b0), "r"(b1))
#define CP_ASYNC16(dst, src, sz) \
    asm volatile("cp.async.cg.shared.global [%0], [%1], 16, %2;" \
        :: "r"((uint32_t)(dst)), "l"(src), "r"((uint32_t)(sz)) : "memory")
#define CP_COMMIT() asm volatile("cp.async.commit_group;" ::: "memory")
#define CP_WAIT0()  asm volatile("cp.async.wait_group 0;" ::: "memory")

// bf16x2 pack: a -> low half, b -> high half
__device__ __forceinline__ uint32_t pack_bf16(float a, float b) {
    uint32_t r;
    asm("cvt.rn.bf16x2.f32 %0, %1, %2;" : "=r"(r) : "f"(b), "f"(a));
    return r;
}
__device__ __forceinline__ void split2(float a, float b, uint32_t& hi, uint32_t& lo) {
    hi = pack_bf16(a, b);
    float ha = __uint_as_float(hi << 16);
    float hb = __uint_as_float(hi & 0xffff0000u);
    lo = pack_bf16(a - ha, b - hb);
}

// ================= kernels =================

__global__ void kern_init(float* __restrict__ out) {
    int i = blockIdx.x * blockDim.x + threadIdx.x;
    if (i < BATCH * KC * FB) out[i] = 0.f;
    if (i < BATCH * KC * KC) { g_outadj[i] = 0.f; g_ss[i] = 0.f; }
}

// ---- fused softmax + transpose + bf16 split: s -> g_sTh/g_sTl [b][64][NPAD], g_q ----
__global__ __launch_bounds__(256) void kern_strans(const float* __restrict__ s) {
    __shared__ float tile[128][65];
    int b = blockIdx.y, n0 = blockIdx.x * 128, t = threadIdx.x;
    int r = t >> 1, half = t & 1;
    int n = n0 + r;
    bool valid = (n < NB);
    float v[32];
    if (valid) {
        const float* sr = s + ((size_t)b * NB + n) * KC + half * 32;
        #pragma unroll
        for (int i = 0; i < 8; i++) *(float4*)&v[i * 4] = *(const float4*)(sr + i * 4);
        float mx = v[0];
        #pragma unroll
        for (int i = 1; i < 32; i++) mx = fmaxf(mx, v[i]);
        mx = fmaxf(mx, __shfl_xor_sync(0xffffffffu, mx, 1));
        float sum = 0.f;
        #pragma unroll
        for (int i = 0; i < 32; i++) { v[i] = __expf(v[i] - mx); sum += v[i]; }
        sum += __shfl_xor_sync(0xffffffffu, sum, 1);
        float inv = 1.f / sum;
        float q = 0.f;
        #pragma unroll
        for (int i = 0; i < 32; i++) { v[i] *= inv; q += v[i] * v[i]; }
        q += __shfl_xor_sync(0xffffffffu, q, 1);
        if (half == 0) g_q[b * NB + n] = q;
    } else {
        #pragma unroll
        for (int i = 0; i < 32; i++) v[i] = 0.f;
        __shfl_xor_sync(0xffffffffu, 0.f, 1);
        __shfl_xor_sync(0xffffffffu, 0.f, 1);
        __shfl_xor_sync(0xffffffffu, 0.f, 1);
    }
    #pragma unroll
    for (int i = 0; i < 32; i++) tile[r][half * 32 + i] = v[i];
    __syncthreads();
    #pragma unroll
    for (int l = 0; l < 8; l++) {
        int fid = t + l * 256;          // 2048 groups of 4
        int k = fid >> 5, nq = (fid & 31) << 2;
        float v0 = tile[nq][k], v1 = tile[nq + 1][k];
        float v2 = tile[nq + 2][k], v3 = tile[nq + 3][k];
        uint32_t h0, l0, h1, l1;
        split2(v0, v1, h0, l0);
        split2(v2, v3, h1, l1);
        size_t dst = ((size_t)b * KC + k) * NPAD + n0 + nq;
        *(uint2*)(g_sTh + dst) = make_uint2(h0, h1);
        *(uint2*)(g_sTl + dst) = make_uint2(l0, l1);
    }
}

// ---- out = s^T x via mma (A = sT bf16, B = x via ldmatrix.trans) ----
__global__ __launch_bounds__(256) void kern_sx_mma(const float* __restrict__ x,
                                                   float* __restrict__ out) {
    __shared__ unsigned short sAh[64 * 40], sAl[64 * 40];     // sT tiles [64][40]
    __shared__ unsigned short sXh[32 * 136], sXl[32 * 136];   // x tiles  [32][136]
    const uint32_t pAh = smem_to_u32(sAh), pAl = smem_to_u32(sAl);
    const uint32_t pXh = smem_to_u32(sXh), pXl = smem_to_u32(sXl);
    int b = blockIdx.y, start = blockIdx.x * 64;
    int t = threadIdx.x, lane = t & 31, w = t >> 5;
    int mslice = (w & 3) * 16, fhalf = (w >> 2) * 64;
    const float* xb = x + (size_t)b * NB * FB;
    float acc[8][4];
    #pragma unroll
    for (int i = 0; i < 8; i++)
        #pragma unroll
        for (int j = 0; j < 4; j++) acc[i][j] = 0.f;

    for (int cb = 0; cb < 2; cb++) {
        int base = start + cb * 32;
        int lim = NB - base;
        {
            int kc = t >> 2, j8 = (t & 3) * 8;
            size_t src = ((size_t)b * KC + kc) * NPAD + base + j8;
            uint4 vh = *(const uint4*)(g_sTh + src);
            uint4 vl = *(const uint4*)(g_sTl + src);
            STSV4U(pAh + (uint32_t)(kc * 40 + j8) * 2, vh);
            STSV4U(pAl + (uint32_t)(kc * 40 + j8) * 2, vl);
        }
        #pragma unroll
        for (int l = 0; l < 4; l++) {
            int fid = t + l * 256;
            int r = fid >> 5, c4 = (fid & 31) * 4;
            float4 v = make_float4(0.f, 0.f, 0.f, 0.f);
            if (r < lim) v = *(const float4*)(xb + (size_t)(base + r) * FB + c4);
            uint32_t h0, l0, h1, l1;
            split2(v.x, v.y, h0, l0);
            split2(v.z, v.w, h1, l1);
            uint32_t off = (uint32_t)(r * 136 + c4) * 2;
            STSV2(pXh + off, h0, h1);
            STSV2(pXl + off, l0, l1);
        }
        __syncthreads();
        #pragma unroll
        for (int ks = 0; ks < 2; ks++) {
            uint32_t ah[4], al[4];
            int arow = mslice + (lane & 15), acol = ks * 16 + (lane >> 4) * 8;
            LDSM4(ah, pAh + (uint32_t)(arow * 40 + acol) * 2);
            LDSM4(al, pAl + (uint32_t)(arow * 40 + acol) * 2);
            uint32_t bh[16], bl[16];
            int kr = ks * 16 + (lane & 15);
            #pragma unroll
            for (int j = 0; j < 4; j++) {
                int nc = fhalf + j * 16 + ((lane >> 4) << 3);
                uint32_t off = (uint32_t)(kr * 136 + nc) * 2;
                LDSM4T(&bh[4 * j], pXh + off);
                LDSM4T(&bl[4 * j], pXl + off);
            }
            #pragma unroll
            for (int nt = 0; nt < 8; nt++) {
                MMA_BF16(acc[nt], ah, bh[2 * nt], bh[2 * nt + 1]);
                MMA_BF16(acc[nt], ah, bl[2 * nt], bl[2 * nt + 1]);
                MMA_BF16(acc[nt], al, bh[2 * nt], bh[2 * nt + 1]);
            }
        }
        __syncthreads();
    }
    int row = mslice + (lane >> 2);
    int col0 = fhalf + 2 * (lane & 3);
    float* ob = out + (size_t)b * KC * FB;
    #pragma unroll
    for (int nt = 0; nt < 8; nt++) {
        atomicAdd(&ob[row * FB + col0 + nt * 8], acc[nt][0]);
        atomicAdd(&ob[row * FB + col0 + nt * 8 + 1], acc[nt][1]);
        atomicAdd(&ob[(row + 8) * FB + col0 + nt * 8], acc[nt][2]);
        atomicAdd(&ob[(row + 8) * FB + col0 + nt * 8 + 1], acc[nt][3]);
    }
}

// ---- as_ = adj @ s: 64-row tiles, 2 CTAs/SM, race-free pipeline ----
// smem layout (bytes):
static constexpr int SMS_AHI = 0;                  // 2 x 9216
static constexpr int SMS_ALO = 18432;              // 2 x 9216
static constexpr int SMS_BHI = 36864;              // 2 x 9216
static constexpr int SMS_BLO = 55296;              // 2 x 9216
static constexpr int SMS_TOTAL = 73728;
// epilogue overlays (after final sync): ash=0, asl=9216, s2h=18432, s2l=27648

__global__ __launch_bounds__(256, 2)
void kern_adjs_mma(const float* __restrict__ adj) {
    extern __shared__ char smem[];
    const uint32_t sb = smem_to_u32(smem);
    const int t = threadIdx.x, lane = t & 31, w = t >> 5;
    const int wm = w & 3, wn = w >> 2;        // warp tile: m16 x n32
    const int b = blockIdx.y, r0 = blockIdx.x * 64;
    const float* adjb = adj + (size_t)b * NB * NB;

    float acc[4][4];
    #pragma unroll
    for (int i = 0; i < 4; i++)
        #pragma unroll
        for (int j = 0; j < 4; j++) acc[i][j] = 0.f;
    float drow[4];
    #pragma unroll
    for (int i = 0; i < 4; i++) drow[i] = 0.f;

    float4 areg[4];

    auto ldgA = [&](int c) {
        int m0 = c * 64;
        #pragma unroll
        for (int i = 0; i < 4; i++) {
            int fid = t + i * 256;            // 1024 float4
            int r = fid >> 4, g = fid & 15;
            int gr = r0 + r, gc = m0 + g * 4;
            float4 v = make_float4(0.f, 0.f, 0.f, 0.f);
            if (gr < NB && gc + 4 <= NB) v = *(const float4*)(adjb + (size_t)gr * NB + gc);
            areg[i] = v;
        }
    };
    auto issueB = [&](int c) {
        int m0 = c * 64;
        #pragma unroll
        for (int i = 0; i < 4; i++) {
            int fid = t + i * 256;            // 1024: 512 hi + 512 lo
            int half = fid >> 9;
            int fm = fid & 511;
            int n = fm >> 3, g = fm & 7;
            const unsigned short* src = (half ? g_sTl : g_sTh)
                + ((size_t)b * KC + n) * NPAD + m0 + g * 8;
            uint32_t dst = sb + (half ? SMS_BLO : SMS_BHI) + (c & 1) * 9216
                         + (uint32_t)((n * 72 + g * 8) * 2);
            CP_ASYNC16(dst, src, 16);
        }
        CP_COMMIT();
    };

    ldgA(0);
    issueB(0);

    for (int c = 0; c < NCH; c++) {
        // convert regs -> bf16 hi/lo STS into A buf[c&1] (+ degree)
        uint32_t aHi = sb + SMS_AHI + (c & 1) * 9216;
        uint32_t aLo = sb + SMS_ALO + (c & 1) * 9216;
        #pragma unroll
        for (int i = 0; i < 4; i++) {
            int fid = t + i * 256;
            int r = fid >> 4, c4 = (fid & 15) << 2;
            float4 v = areg[i];
            drow[i] += (v.x + v.y) + (v.z + v.w);
            uint32_t h0, l0, h1, l1;
            split2(v.x, v.y, h0, l0);
            split2(v.z, v.w, h1, l1);
            uint32_t offs = (uint32_t)((r * 72 + c4) * 2);
            STSV2(aHi + offs, h0, h1);
            STSV2(aLo + offs, l0, l1);
        }
        if (c + 1 < NCH) ldgA(c + 1);     // LDG latency hides across sync + mma
        CP_WAIT0();                       // B(c) landed
        __syncthreads();                  // all warps done with mma(c-1) buffers
        if (c + 1 < NCH) issueB(c + 1);   // safe: writes buf[(c+1)&1], all readers past

        // mma: warp (wm, wn) does rows wm*16.., cols wn*32..+31
        uint32_t bHiB = sb + SMS_BHI + (c & 1) * 9216;
        uint32_t bLoB = sb + SMS_BLO + (c & 1) * 9216;
        int bn = (lane & 7) + ((lane >> 4) << 3);
        int bk = ((lane >> 3) & 1) * 8;
        #pragma unroll
        for (int ks = 0; ks < 4; ks++) {
            uint32_t ah[4], al[4];
            int arow = wm * 16 + (lane & 15);
            int acol = ks * 16 + (lane >> 4) * 8;
            LDSM4(ah, aHi + (uint32_t)((arow * 72 + acol) * 2));
            LDSM4(al, aLo + (uint32_t)((arow * 72 + acol) * 2));
            uint32_t bh[8], bl[8];
            #pragma unroll
            for (int j = 0; j < 2; j++) {
                int brow = wn * 32 + 16 * j + bn;
                uint32_t off = (uint32_t)((brow * 72 + ks * 16 + bk) * 2);
                LDSM4(&bh[4 * j], bHiB + off);
                LDSM4(&bl[4 * j], bLoB + off);
            }
            #pragma unroll
            for (int nt = 0; nt < 4; nt++) {
                MMA_BF16(acc[nt], ah, bh[2 * nt], bh[2 * nt + 1]);
                MMA_BF16(acc[nt], ah, bl[2 * nt], bl[2 * nt + 1]);
                MMA_BF16(acc[nt], al, bh[2 * nt], bh[2 * nt + 1]);
            }
        }
    }

    // degree writeback: 16 threads per row
    #pragma unroll
    for (int i = 0; i < 4; i++) {
        float d = drow[i];
        #pragma unroll
        for (int o = 1; o < 16; o <<= 1) d += __shfl_xor_sync(0xffffffffu, d, o);
        int r = (t >> 4) + 16 * i;
        if ((t & 15) == 0 && r0 + r < NB) g_dflat[b * NB + r0 + r] = d;
    }

    // ================= fused pool epilogue =================
    __syncthreads();   // all warps done with main-loop smem
    const uint32_t ashp = sb;                           // [64][72] halfs
    const uint32_t aslp = sb + 9216;
    const uint32_t s2h  = sb + 18432;                   // [64][72] halfs
    const uint32_t s2l  = sb + 27648;
    // store acc -> ash/asl (bf16 split); warp (wm, wn) owns its quadrant
    {
        int cq = 2 * (lane & 3);
        int rb = wm * 16 + (lane >> 2);
        #pragma unroll
        for (int nt = 0; nt < 4; nt++) {
            int col = wn * 32 + nt * 8 + cq;
            uint32_t h, l;
            split2(acc[nt][0], acc[nt][1], h, l);
            STS32(ashp + (uint32_t)(rb * 72 + col) * 2, h);
            STS32(aslp + (uint32_t)(rb * 72 + col) * 2, l);
            split2(acc[nt][2], acc[nt][3], h, l);
            STS32(ashp + (uint32_t)((rb + 8) * 72 + col) * 2, h);
            STS32(aslp + (uint32_t)((rb + 8) * 72 + col) * 2, l);
        }
    }
    // load sT2 = sT[:, r0:r0+64] hi/lo -> [64][72]
    #pragma unroll
    for (int i = 0; i < 2; i++) {
        int fid = t + i * 256;               // 512 uint4
        int kc = fid >> 3, j8 = (fid & 7) * 8;
        size_t src = ((size_t)b * KC + kc) * NPAD + r0 + j8;
        uint4 vh = *(const uint4*)(g_sTh + src);
        uint4 vl = *(const uint4*)(g_sTl + src);
        STSV4U(s2h + (uint32_t)(kc * 72 + j8) * 2, vh);
        STSV4U(s2l + (uint32_t)(kc * 72 + j8) * 2, vl);
    }
    __syncthreads();
    // epilogue mma: out_adj += as^T s ; ss += sT2 sT2^T (contraction = 64 rows)
    {
        int msl = wm * 16, nh = wn * 32;
        float accO[4][4], accS[4][4];
        #pragma unroll
        for (int i = 0; i < 4; i++)
            #pragma unroll
            for (int j = 0; j < 4; j++) { accO[i][j] = 0.f; accS[i][j] = 0.f; }
        int krow = (lane & 7) + ((lane >> 4) << 3);
        int mcol = msl + (((lane >> 3) & 1) << 3);
        int arow = msl + (lane & 15);
        int bn = (lane & 7) + ((lane >> 4) << 3);
        int bk8 = ((lane >> 3) & 1) * 8;
        #pragma unroll
        for (int ks = 0; ks < 4; ks++) {
            uint32_t aOh[4], aOl[4];
            LDSM4T(aOh, ashp + (uint32_t)(((ks * 16 + krow) * 72 + mcol) * 2));
            LDSM4T(aOl, aslp + (uint32_t)(((ks * 16 + krow) * 72 + mcol) * 2));
            uint32_t aSh[4], aSl[4];
            int acol = ks * 16 + (lane >> 4) * 8;
            LDSM4(aSh, s2h + (uint32_t)((arow * 72 + acol) * 2));
            LDSM4(aSl, s2l + (uint32_t)((arow * 72 + acol) * 2));
            uint32_t bh[8], bl[8];
            #pragma unroll
            for (int j = 0; j < 2; j++) {
                int brow = nh + 16 * j + bn;
                uint32_t off = (uint32_t)((brow * 72 + ks * 16 + bk8) * 2);
                LDSM4(&bh[4 * j], s2h + off);
                LDSM4(&bl[4 * j], s2l + off);
            }
            #pragma unroll
            for (int nt = 0; nt < 4; nt++) {
                MMA_BF16(accO[nt], aOh, bh[2 * nt], bh[2 * nt + 1]);
                MMA_BF16(accO[nt], aOh, bl[2 * nt], bl[2 * nt + 1]);
                MMA_BF16(accO[nt], aOl, bh[2 * nt], bh[2 * nt + 1]);
                MMA_BF16(accS[nt], aSh, bh[2 * nt], bh[2 * nt + 1]);
                MMA_BF16(accS[nt], aSh, bl[2 * nt], bl[2 * nt + 1]);
                MMA_BF16(accS[nt], aSl, bh[2 * nt], bh[2 * nt + 1]);
            }
        }
        int row = msl + (lane >> 2);
        int cq = 2 * (lane & 3);
        float* oadj = g_outadj + b * KC * KC;
        float* oss  = g_ss + b * KC * KC;
        #pragma unroll
        for (int nt = 0; nt < 4; nt++) {
            int col = nh + nt * 8 + cq;
            atomicAdd(&oadj[row * KC + col], accO[nt][0]);
            atomicAdd(&oadj[row * KC + col + 1], accO[nt][1]);
            atomicAdd(&oadj[(row + 8) * KC + col], accO[nt][2]);
            atomicAdd(&oadj[(row + 8) * KC + col + 1], accO[nt][3]);
            atomicAdd(&oss[row * KC + col], accS[nt][0]);
            atomicAdd(&oss[row * KC + col + 1], accS[nt][1]);
            atomicAdd(&oss[(row + 8) * KC + col], accS[nt][2]);
            atomicAdd(&oss[(row + 8) * KC + col + 1], accS[nt][3]);
        }
    }
}

__device__ __forceinline__ float blockReduceSum(float v, float* red) {
    int t = threadIdx.x;
    red[t] = v;
    __syncthreads();
    for (int o = 128; o; o >>= 1) {
        if (t < o) red[t] += red[t + o];
        __syncthreads();
    }
    float r = red[0];
    __syncthreads();
    return r;
}

// ---- per-batch: losses + final out_adj normalization ----
__global__ __launch_bounds__(256) void kern_final(float* __restrict__ dout) {
    __shared__ float adjm[KC * KC];
    __shared__ float red[256];
    __shared__ float dd[KC];
    int b = blockIdx.x, t = threadIdx.x;
    for (int i = t; i < KC * KC; i += 256) adjm[i] = g_outadj[b * KC * KC + i];
    __syncthreads();

    float loc = 0.f;
    for (int i = t; i < KC; i += 256) loc += adjm[i * (KC + 1)];
    float tr = blockReduceSum(loc, red);

    loc = 0.f;
    for (int n = t; n < NB; n += 256) loc += g_dflat[b * NB + n] * g_q[b * NB + n];
    float den = blockReduceSum(loc, red);

    loc = 0.f;
    for (int i = t; i < KC * KC; i += 256) { float v = g_ss[b * KC * KC + i]; loc += v * v; }
    float ssn = sqrtf(blockReduceSum(loc, red));

    loc = 0.f;
    for (int i = t; i < KC * KC; i += 256) {
        float v = g_ss[b * KC * KC + i] / ssn;
        if ((i >> 6) == (i & 63)) v -= 0.125f;
        loc += v * v;
    }
    float orth = sqrtf(blockReduceSum(loc, red));

    if (t == 0) { g_bloss[b] = -(tr / den); g_bloss[BATCH + b] = orth; }

    if (t < KC) adjm[t * (KC + 1)] = 0.f;
    __syncthreads();
    if (t < KC) {
        float rs = 0.f;
        for (int j = 0; j < KC; j++) rs += adjm[t * KC + j];
        dd[t] = sqrtf(rs) + 1e-15f;
    }
    __syncthreads();
    for (int i = t; i < KC * KC; i += 256) {
        int r = i >> 6, c = i & 63;
        dout[BATCH * KC * FB + b * KC * KC + i] = adjm[i] / (dd[r] * dd[c]);
    }
}

__global__ void kern_mean(float* __restrict__ dout) {
    int t = threadIdx.x;
    float m = (t < BATCH) ? g_bloss[t] : 0.f;
    float o = (t < BATCH) ? g_bloss[BATCH + t] : 0.f;
    #pragma unroll
    for (int off = 16; off; off >>= 1) {
        m += __shfl_xor_sync(0xffffffffu, m, off);
        o += __shfl_xor_sync(0xffffffffu, o, off);
    }
    if (t == 0) {
        dout[BATCH * KC * FB + BATCH * KC * KC]     = m / (float)BATCH;
        dout[BATCH * KC * FB + BATCH * KC * KC + 1] = o / (float)BATCH;
    }
}

extern "C" void kernel_launch(void* const* d_in, const int* in_sizes, int n_in,
                              void* d_out, int out_size) {
    const float* x   = (const float*)d_in[0];
    const float* adj = (const float*)d_in[1];
    const float* s   = (const float*)d_in[2];
    (void)in_sizes; (void)n_in; (void)out_size;
    float* out = (float*)d_out;

    cudaFuncSetAttribute(kern_adjs_mma, cudaFuncAttributeMaxDynamicSharedMemorySize, SMS_TOTAL);

    kern_init<<<(BATCH * KC * FB + 255) / 256, 256>>>(out);
    kern_strans<<<dim3(16, BATCH), 256>>>(s);
    kern_sx_mma<<<dim3(32, BATCH), 256>>>(x, out);
    kern_adjs_mma<<<dim3(32, BATCH), 256, SMS_TOTAL>>>(adj);
    kern_final<<<BATCH, 256>>>(out);
    kern_mean<<<1, 32>>>(out);
}